// round 1
// baseline (speedup 1.0000x reference)
#include <cuda_runtime.h>
#include <math.h>

#define NB 32
#define NT 512
#define NE 300
#define NH 512
#define NG 2048   // 4*NH

#define NCTA_B 128
#define THR_B  256

#define US_STRIDE 20
#define HS_STRIDE 36
#define RED_STRIDE 17

// Scratch (device globals: allocation-free rule)
__device__ float g_xz[(size_t)NT * NG * NB];   // [t][n][b]  (128 MB)
__device__ float g_h[2][NH * NB];              // ping-pong h, layout [k][b]
__device__ unsigned int g_bar;

// ---------------------------------------------------------------------------
// Init: zero h buffers + barrier counter (re-run every launch: deterministic)
// ---------------------------------------------------------------------------
__global__ void init_kernel() {
    int tid = blockIdx.x * blockDim.x + threadIdx.x;
    if (tid == 0) g_bar = 0u;
    for (int i = tid; i < 2 * NH * NB; i += blockDim.x * gridDim.x)
        ((float*)g_h)[i] = 0.f;
}

// ---------------------------------------------------------------------------
// Kernel A: xz[t][n][b] = sum_k emb[tok(b,t)][k] * W[k][n] + bias[n]
// M = t*32+b (16384), N = 2048, K = 300. Tiles 64x64, BK=10, thread tile 4x4.
// ---------------------------------------------------------------------------
__global__ __launch_bounds__(256) void xz_kernel(
    const int* __restrict__ tokens, const float* __restrict__ emb,
    const float* __restrict__ W, const float* __restrict__ bias)
{
    __shared__ float As[10 * 64];
    __shared__ float Bs[10 * 64];
    __shared__ int   toks[64];

    int tid = threadIdx.x;
    int m0 = blockIdx.y * 64;
    int n0 = blockIdx.x * 64;

    if (tid < 64) {
        int m = m0 + tid;                 // m = t*32 + b
        toks[tid] = tokens[(m & 31) * NT + (m >> 5)];   // tokens[b][t]
    }
    __syncthreads();

    int tm = tid & 15, tn = tid >> 4;
    float acc[4][4] = {};

    for (int k0 = 0; k0 < NE; k0 += 10) {
        int idx = tid;                    // 640 elements each
        #pragma unroll
        for (int r = 0; r < 3; ++r) {
            if (idx < 640) {
                int kk = idx >> 6, i = idx & 63;
                As[kk * 64 + i] = emb[(size_t)toks[i] * NE + k0 + kk];
                Bs[kk * 64 + i] = W[(size_t)(k0 + kk) * NG + n0 + i];
            }
            idx += 256;
        }
        __syncthreads();
        #pragma unroll
        for (int kk = 0; kk < 10; ++kk) {
            float4 av = *(const float4*)&As[kk * 64 + tm * 4];
            float4 bv = *(const float4*)&Bs[kk * 64 + tn * 4];
            float a[4] = {av.x, av.y, av.z, av.w};
            float b[4] = {bv.x, bv.y, bv.z, bv.w};
            #pragma unroll
            for (int i = 0; i < 4; ++i)
                #pragma unroll
                for (int j = 0; j < 4; ++j)
                    acc[i][j] += a[i] * b[j];
        }
        __syncthreads();
    }

    #pragma unroll
    for (int j = 0; j < 4; ++j) {
        int n = n0 + tn * 4 + j;
        float bb = bias[n];
        #pragma unroll
        for (int i = 0; i < 4; ++i) {
            int mi = tm * 4 + i;
            int t = (m0 + mi) >> 5;
            int b = (m0 + mi) & 31;
            g_xz[(size_t)t * (NG * NB) + (size_t)n * NB + b] = acc[i][j] + bb;
        }
    }
}

// ---------------------------------------------------------------------------
// Kernel B: persistent LSTM recurrence. 128 CTAs; CTA owns 4 h-columns (j)
// across all 4 gates (16 U columns, kept in smem). c kept in smem per CTA.
// Per step: z = xz[t] + h @ U ; gates ; write new h to global ping-pong;
// software grid barrier.
// ---------------------------------------------------------------------------
__global__ __launch_bounds__(THR_B) void lstm_kernel(
    const float* __restrict__ U, float* __restrict__ out)
{
    extern __shared__ float sm[];
    float* us  = sm;                          // [512][US_STRIDE]  (16 used)
    float* hs  = us  + NH * US_STRIDE;        // [512][HS_STRIDE]  (32 used)
    float* red = hs  + NH * HS_STRIDE;        // [16*32][RED_STRIDE] (16 used)
    float* zs  = red + 16 * 32 * RED_STRIDE;  // [512]
    float* cs  = zs  + 512;                   // [128]  c[jj][b]

    int tid = threadIdx.x;
    int cta = blockIdx.x;
    int j0 = cta * 4;

    // Load U slice: us[k][c], c = sigma*4 + jj  ->  U[k][sigma*512 + j0 + jj]
    for (int idx = tid; idx < NH * 16; idx += THR_B) {
        int k = idx >> 4, c = idx & 15;
        int col = (c >> 2) * NH + j0 + (c & 3);
        us[k * US_STRIDE + c] = U[(size_t)k * NG + col];
    }
    if (tid < 128) cs[tid] = 0.f;
    __syncthreads();

    int kt = tid >> 4, ot = tid & 15;        // kt: K-split 16, ot: output tile
    int b0 = (ot & 3) * 8;                   // 8 batches
    int n0 = (ot >> 2) * 4;                  // 4 gate-cols
    int kbase = kt * 32;

    for (int t = 0; t < NT; ++t) {
        int parity = t & 1;

        // Copy h (L2-coherent: bypass L1, other SMs wrote it last step)
        const float4* gh4 = (const float4*)g_h[parity];
        for (int i4 = tid; i4 < (NH * NB) / 4; i4 += THR_B) {
            float4 v = __ldcg(gh4 + i4);
            int base = i4 * 4;
            int k = base >> 5, b = base & 31;
            float* d = hs + k * HS_STRIDE + b;
            d[0] = v.x; d[1] = v.y; d[2] = v.z; d[3] = v.w;
        }
        __syncthreads();

        // Partial GEMM: acc[8b][4n] over K slice of 32
        float acc[8][4];
        #pragma unroll
        for (int i = 0; i < 8; ++i)
            #pragma unroll
            for (int j = 0; j < 4; ++j) acc[i][j] = 0.f;

        #pragma unroll 4
        for (int k = 0; k < 32; ++k) {
            int kk = kbase + k;
            const float* hrow = hs + kk * HS_STRIDE + b0;
            float4 h0 = *(const float4*)(hrow);
            float4 h1 = *(const float4*)(hrow + 4);
            float4 uv = *(const float4*)(us + kk * US_STRIDE + n0);
            float hv[8] = {h0.x, h0.y, h0.z, h0.w, h1.x, h1.y, h1.z, h1.w};
            float uu[4] = {uv.x, uv.y, uv.z, uv.w};
            #pragma unroll
            for (int i = 0; i < 8; ++i)
                #pragma unroll
                for (int j = 0; j < 4; ++j)
                    acc[i][j] += hv[i] * uu[j];
        }

        // K-split reduction through smem
        #pragma unroll
        for (int i = 0; i < 8; ++i)
            #pragma unroll
            for (int j = 0; j < 4; ++j)
                red[((n0 + j) * 32 + (b0 + i)) * RED_STRIDE + kt] = acc[i][j];
        __syncthreads();

        #pragma unroll
        for (int r = 0; r < 2; ++r) {
            int o = tid * 2 + r;                       // 512 outputs
            const float* p = red + o * RED_STRIDE;
            float s = 0.f;
            #pragma unroll
            for (int q = 0; q < 16; ++q) s += p[q];
            zs[o] = s;
        }
        __syncthreads();

        // Gates + state update: thread = (jj, b), 128 threads
        if (tid < 128) {
            int jj = tid >> 5, b = tid & 31;
            size_t xbase = (size_t)t * (NG * NB) + (size_t)(j0 + jj) * NB + b;
            float zi = zs[(0 * 4 + jj) * 32 + b] + g_xz[xbase + (size_t)0 * NH * NB];
            float zf = zs[(1 * 4 + jj) * 32 + b] + g_xz[xbase + (size_t)1 * NH * NB];
            float zg = zs[(2 * 4 + jj) * 32 + b] + g_xz[xbase + (size_t)2 * NH * NB];
            float zo = zs[(3 * 4 + jj) * 32 + b] + g_xz[xbase + (size_t)3 * NH * NB];

            float ig = 1.f / (1.f + expf(-zi));
            float fg = 1.f / (1.f + expf(-zf));
            float gg = tanhf(zg);
            float og = 1.f / (1.f + expf(-zo));

            float cn = fg * cs[tid] + ig * gg;
            cs[tid] = cn;
            float hn = og * tanhf(cn);

            if (t == NT - 1) {
                out[b * NH + (j0 + jj)] = hn;                 // hidden [B,H]
                out[NB * NH + b * NH + (j0 + jj)] = cn;       // cell   [B,H]
            } else {
                g_h[parity ^ 1][(j0 + jj) * NB + b] = hn;
            }
        }

        // Grid-wide barrier (monotonic counter; all 128 CTAs co-resident)
        if (t < NT - 1) {
            __threadfence();
            __syncthreads();
            if (tid == 0) {
                atomicAdd(&g_bar, 1u);
                unsigned target = (unsigned)NCTA_B * (unsigned)(t + 1);
                while (*((volatile unsigned int*)&g_bar) < target) { }
            }
            __syncthreads();
        }
    }
}

// ---------------------------------------------------------------------------
extern "C" void kernel_launch(void* const* d_in, const int* in_sizes, int n_in,
                              void* d_out, int out_size) {
    const int*   tokens = (const int*)d_in[0];
    const float* emb    = (const float*)d_in[1];
    const float* W      = (const float*)d_in[2];
    const float* U      = (const float*)d_in[3];
    const float* bias   = (const float*)d_in[4];
    float* out = (float*)d_out;

    init_kernel<<<32, 256>>>();

    dim3 ga(NG / 64, (NB * NT) / 64);   // (32, 256)
    xz_kernel<<<ga, 256>>>(tokens, emb, W, bias);

    int smem = (NH * US_STRIDE + NH * HS_STRIDE + 16 * 32 * RED_STRIDE + 512 + 128)
               * (int)sizeof(float);    // 152064 B
    cudaFuncSetAttribute(lstm_kernel, cudaFuncAttributeMaxDynamicSharedMemorySize, smem);
    lstm_kernel<<<NCTA_B, THR_B, smem>>>(U, out);
}

// round 2
// speedup vs baseline: 1.1208x; 1.1208x over previous
#include <cuda_runtime.h>
#include <math.h>

#define NB 32
#define NT 512
#define NE 300
#define NH 512
#define NG 2048   // 4*NH

#define NCTA_B 128
#define THR_B  256

#define HS_STRIDE 36          // floats per h row (32 used)
#define US_STRIDE 18          // u64 per U row (16 used)
#define RED_ROW   520         // floats per kt row (512 used)

typedef unsigned long long u64;

// ---------------------------------------------------------------------------
// f32x2 helpers (Blackwell packed fp32 — 2x FFMA throughput, full precision)
// ---------------------------------------------------------------------------
__device__ __forceinline__ u64 pack2(float lo, float hi) {
    u64 r; asm("mov.b64 %0, {%1,%2};" : "=l"(r) : "f"(lo), "f"(hi)); return r;
}
__device__ __forceinline__ void fma2(u64& d, u64 a, u64 b) {
    asm("fma.rn.f32x2 %0, %1, %2, %0;" : "+l"(d) : "l"(a), "l"(b));
}
__device__ __forceinline__ float2 unpack2(u64 v) {
    float2 f; asm("mov.b64 {%0,%1}, %2;" : "=f"(f.x), "=f"(f.y) : "l"(v)); return f;
}

__device__ __forceinline__ float fast_sig(float x) {
    float e = __expf(-x);
    return __fdividef(1.f, 1.f + e);
}
__device__ __forceinline__ float fast_tanh(float x) {
    float e = __expf(2.f * x);              // inf-safe: ->1 / ->-1 at extremes
    return 1.f - 2.f * __fdividef(1.f, e + 1.f);
}

// Scratch (device globals: allocation-free rule)
__device__ float g_xz[(size_t)NT * NG * NB];   // [t][n][b]
__device__ float g_h[2][NH * NB];              // ping-pong h, [k][b]
__device__ unsigned int g_bar;

// ---------------------------------------------------------------------------
__global__ void init_kernel() {
    int tid = blockIdx.x * blockDim.x + threadIdx.x;
    if (tid == 0) g_bar = 0u;
    for (int i = tid; i < 2 * NH * NB; i += blockDim.x * gridDim.x)
        ((float*)g_h)[i] = 0.f;
}

// ---------------------------------------------------------------------------
// Kernel A: xz[t][n][b] = sum_k emb[tok(b,t)][k] * W[k][n] + bias[n]
// Tiles 64(M)x64(N), BK=25 (300=12*25). Coalesced emb row loads; W duplicated
// into f32x2 pairs once in smem; inner loop = 3 LDS.128 + 8 FFMA2 per thread.
// ---------------------------------------------------------------------------
__global__ __launch_bounds__(256) void xz_kernel(
    const int* __restrict__ tokens, const float* __restrict__ emb,
    const float* __restrict__ W, const float* __restrict__ bias)
{
    __shared__ float As[25 * 68];        // [kk][m], stride 68
    __shared__ u64   Bs2[25 * 68];       // [kk][n] duplicated pairs, stride 68
    __shared__ int   toks[64];

    int tid = threadIdx.x;
    int m0 = blockIdx.y * 64;
    int n0 = blockIdx.x * 64;

    if (tid < 64) {
        int m = m0 + tid;                               // m = t*32 + b
        toks[tid] = tokens[(m & 31) * NT + (m >> 5)];   // tokens[b][t]
    }
    __syncthreads();

    int tm = tid & 15, tn = tid >> 4;
    u64 acc2[2][4];
    #pragma unroll
    for (int p = 0; p < 2; ++p)
        #pragma unroll
        for (int j = 0; j < 4; ++j) acc2[p][j] = 0ull;

    for (int k0 = 0; k0 < NE; k0 += 25) {
        // As: row-coalesced gather of emb rows (25 contiguous floats each)
        for (int idx = tid; idx < 64 * 25; idx += 256) {
            int m = idx / 25, kk = idx - m * 25;
            As[kk * 68 + m] = emb[(size_t)toks[m] * NE + k0 + kk];
        }
        // Bs2: coalesced W rows, stored as duplicated f32x2 pairs
        for (int idx = tid; idx < 25 * 64; idx += 256) {
            int kk = idx >> 6, n = idx & 63;
            float w = W[(size_t)(k0 + kk) * NG + n0 + n];
            Bs2[kk * 68 + n] = pack2(w, w);
        }
        __syncthreads();

        #pragma unroll
        for (int kk = 0; kk < 25; ++kk) {
            float4 av = *(const float4*)&As[kk * 68 + tm * 4];
            ulonglong2 b01 = *(const ulonglong2*)&Bs2[kk * 68 + tn * 4];
            ulonglong2 b23 = *(const ulonglong2*)&Bs2[kk * 68 + tn * 4 + 2];
            u64 ap[2] = { pack2(av.x, av.y), pack2(av.z, av.w) };
            u64 bd[4] = { b01.x, b01.y, b23.x, b23.y };
            #pragma unroll
            for (int p = 0; p < 2; ++p)
                #pragma unroll
                for (int j = 0; j < 4; ++j)
                    fma2(acc2[p][j], ap[p], bd[j]);
        }
        __syncthreads();
    }

    #pragma unroll
    for (int j = 0; j < 4; ++j) {
        int n = n0 + tn * 4 + j;
        float bb = bias[n];
        #pragma unroll
        for (int p = 0; p < 2; ++p) {
            float2 v = unpack2(acc2[p][j]);
            int mi0 = m0 + tm * 4 + p * 2;
            int t0 = mi0 >> 5, b0 = mi0 & 31;
            int t1 = (mi0 + 1) >> 5, b1 = (mi0 + 1) & 31;
            __stcs(&g_xz[(size_t)t0 * (NG * NB) + (size_t)n * NB + b0], v.x + bb);
            __stcs(&g_xz[(size_t)t1 * (NG * NB) + (size_t)n * NB + b1], v.y + bb);
        }
    }
}

// ---------------------------------------------------------------------------
// Kernel B: persistent LSTM. 128 CTAs x 256 thr; CTA owns 4 h-cols across 4
// gates (16 U cols, duplicated f32x2 pairs in smem). 16-way K-split + smem
// reduce. xz prefetched into regs; f32x2 inner loop; software grid barrier.
// ---------------------------------------------------------------------------
__global__ __launch_bounds__(THR_B) void lstm_kernel(
    const float* __restrict__ U, float* __restrict__ out)
{
    extern __shared__ float sm[];
    u64*   us2 = (u64*)sm;                      // [512][US_STRIDE] u64
    float* hs  = (float*)(us2 + NH * US_STRIDE);// [512][HS_STRIDE]
    float* red = hs + NH * HS_STRIDE;           // [16][RED_ROW]
    float* zs  = red + 16 * RED_ROW;            // [512]
    float* cs  = zs + 512;                      // [128]

    int tid = threadIdx.x;
    int cta = blockIdx.x;
    int j0 = cta * 4;

    // Load U slice as duplicated pairs: col c = sigma*4+jj -> U[k][sigma*512+j0+jj]
    for (int idx = tid; idx < NH * 16; idx += THR_B) {
        int k = idx >> 4, c = idx & 15;
        int col = (c >> 2) * NH + j0 + (c & 3);
        float u = U[(size_t)k * NG + col];
        us2[k * US_STRIDE + c] = pack2(u, u);
    }
    if (tid < 128) cs[tid] = 0.f;
    __syncthreads();

    int kt = tid >> 4, ot = tid & 15;
    int b0 = (ot & 3) * 8;                      // 8 batches (4 f32x2 pairs)
    int n0 = (ot >> 2) * 4;                     // 4 gate-cols
    int kbase = kt * 32;
    int jj = tid >> 5, bb = tid & 31;           // gates mapping (tid<128)

    for (int t = 0; t < NT; ++t) {
        int parity = t & 1;

        // Prefetch xz for this step (DRAM latency hides under copy+GEMM)
        float x0 = 0.f, x1 = 0.f, x2 = 0.f, x3 = 0.f;
        if (tid < 128) {
            size_t xbase = (size_t)t * (NG * NB) + (size_t)(j0 + jj) * NB + bb;
            x0 = __ldcs(&g_xz[xbase]);
            x1 = __ldcs(&g_xz[xbase + (size_t)1 * NH * NB]);
            x2 = __ldcs(&g_xz[xbase + (size_t)2 * NH * NB]);
            x3 = __ldcs(&g_xz[xbase + (size_t)3 * NH * NB]);
        }

        // Copy h from global (L2-coherent) into smem, vectorized
        const float4* gh4 = (const float4*)g_h[parity];
        for (int i4 = tid; i4 < (NH * NB) / 4; i4 += THR_B) {
            float4 v = __ldcg(gh4 + i4);
            int base = i4 * 4;
            int k = base >> 5, b = base & 31;
            *(float4*)(hs + k * HS_STRIDE + b) = v;
        }
        __syncthreads();

        // Partial GEMM over K slice of 32: 4 LDS.128 + 16 FFMA2 per k
        u64 acc2[4][4];
        #pragma unroll
        for (int i = 0; i < 4; ++i)
            #pragma unroll
            for (int j = 0; j < 4; ++j) acc2[i][j] = 0ull;

        #pragma unroll 4
        for (int k = 0; k < 32; ++k) {
            int kk = kbase + k;
            const float* hrow = hs + kk * HS_STRIDE + b0;
            ulonglong2 ha = *(const ulonglong2*)hrow;
            ulonglong2 hb = *(const ulonglong2*)(hrow + 4);
            const u64* urow = us2 + kk * US_STRIDE + n0;
            ulonglong2 ua = *(const ulonglong2*)urow;
            ulonglong2 ub = *(const ulonglong2*)(urow + 2);
            u64 hp[4] = { ha.x, ha.y, hb.x, hb.y };
            u64 up[4] = { ua.x, ua.y, ub.x, ub.y };
            #pragma unroll
            for (int i = 0; i < 4; ++i)
                #pragma unroll
                for (int j = 0; j < 4; ++j)
                    fma2(acc2[i][j], hp[i], up[j]);
        }

        // K-split reduction: vectorized STS into red[kt][n*32+b]
        #pragma unroll
        for (int j = 0; j < 4; ++j) {
            float2 v0 = unpack2(acc2[0][j]);
            float2 v1 = unpack2(acc2[1][j]);
            float2 v2 = unpack2(acc2[2][j]);
            float2 v3 = unpack2(acc2[3][j]);
            float* dst = red + kt * RED_ROW + (n0 + j) * 32 + b0;
            *(float4*)dst       = make_float4(v0.x, v0.y, v1.x, v1.y);
            *(float4*)(dst + 4) = make_float4(v2.x, v2.y, v3.x, v3.y);
        }
        __syncthreads();

        #pragma unroll
        for (int r = 0; r < 2; ++r) {
            int o = tid * 2 + r;
            float s = 0.f;
            #pragma unroll
            for (int q = 0; q < 16; ++q) s += red[q * RED_ROW + o];
            zs[o] = s;
        }
        __syncthreads();

        // Gates + state update
        if (tid < 128) {
            float zi = zs[(0 * 4 + jj) * 32 + bb] + x0;
            float zf = zs[(1 * 4 + jj) * 32 + bb] + x1;
            float zg = zs[(2 * 4 + jj) * 32 + bb] + x2;
            float zo = zs[(3 * 4 + jj) * 32 + bb] + x3;

            float ig = fast_sig(zi);
            float fg = fast_sig(zf);
            float gg = fast_tanh(zg);
            float og = fast_sig(zo);

            float cn = fg * cs[tid] + ig * gg;
            cs[tid] = cn;
            float hn = og * fast_tanh(cn);

            if (t == NT - 1) {
                out[bb * NH + (j0 + jj)] = hn;             // hidden [B,H]
                out[NB * NH + bb * NH + (j0 + jj)] = cn;   // cell   [B,H]
            } else {
                g_h[parity ^ 1][(j0 + jj) * NB + bb] = hn;
            }
        }

        // Grid-wide barrier
        if (t < NT - 1) {
            __threadfence();
            __syncthreads();
            if (tid == 0) {
                atomicAdd(&g_bar, 1u);
                unsigned target = (unsigned)NCTA_B * (unsigned)(t + 1);
                while (*((volatile unsigned int*)&g_bar) < target) { }
            }
            __syncthreads();
        }
    }
}

// ---------------------------------------------------------------------------
extern "C" void kernel_launch(void* const* d_in, const int* in_sizes, int n_in,
                              void* d_out, int out_size) {
    const int*   tokens = (const int*)d_in[0];
    const float* emb    = (const float*)d_in[1];
    const float* W      = (const float*)d_in[2];
    const float* U      = (const float*)d_in[3];
    const float* bias   = (const float*)d_in[4];
    float* out = (float*)d_out;

    init_kernel<<<32, 256>>>();

    dim3 ga(NG / 64, (NB * NT) / 64);   // (32, 256)
    xz_kernel<<<ga, 256>>>(tokens, emb, W, bias);

    int smem = (int)(NH * US_STRIDE * sizeof(u64) +
                     (NH * HS_STRIDE + 16 * RED_ROW + 512 + 128) * sizeof(float));
    cudaFuncSetAttribute(lstm_kernel, cudaFuncAttributeMaxDynamicSharedMemorySize, smem);
    lstm_kernel<<<NCTA_B, THR_B, smem>>>(U, out);
}